// round 4
// baseline (speedup 1.0000x reference)
#include <cuda_runtime.h>

#define RNUM 4
#define NNODE 100000
#define NEDGE 1000000
#define DH 128
#define GNUM 256
#define NC 10
#define NB 98   // ceil(NNODE/1024)

#define LPAD 132                       // padded K stride for smem tiles
#define SMEM_BYTES (2 * 128 * LPAD * 4)

// ---------------- static device scratch (no allocations allowed) ----------------
__device__ int   g_cnt_out[RNUM * NNODE];
__device__ int   g_cnt_in [RNUM * NNODE];
__device__ float g_rs_out [RNUM * NNODE];
__device__ float g_rs_in  [RNUM * NNODE];
__device__ int   g_rowstart[RNUM * (NNODE + 1)];
__device__ int   g_cursor [RNUM * NNODE];
__device__ int   g_csr    [RNUM * NEDGE];
__device__ int   g_bsum   [RNUM * NB];
__device__ float g_h      [2 * (size_t)NNODE * DH];     // ping-pong hidden states
__device__ float g_hg     [GNUM * DH];
__device__ int   g_gcnt   [GNUM];

// ---------------- init ----------------
__global__ void k_zero() {
    int i = blockIdx.x * blockDim.x + threadIdx.x;
    if (i < RNUM * NNODE) { g_cnt_out[i] = 0; g_cnt_in[i] = 0; }
    if (i < GNUM * DH) g_hg[i] = 0.f;
    if (i < GNUM) g_gcnt[i] = 0;
}

// ---------------- degree counting ----------------
__global__ void k_count(const int* __restrict__ edges) {
    int i = blockIdx.x * blockDim.x + threadIdx.x;
    if (i >= RNUM * NEDGE) return;
    int r = i / NEDGE, e = i % NEDGE;
    int src = edges[(size_t)r * 2 * NEDGE + e];
    int dst = edges[(size_t)r * 2 * NEDGE + NEDGE + e];
    atomicAdd(&g_cnt_out[r * NNODE + src], 1);
    atomicAdd(&g_cnt_in [r * NNODE + dst], 1);
}

// ---------------- scan phase A: per-block sums of in-degree ----------------
__global__ void k_scanA() {
    int r = blockIdx.y;
    int i = blockIdx.x * 1024 + threadIdx.x;
    int v = (i < NNODE) ? g_cnt_in[r * NNODE + i] : 0;
    __shared__ int ws[32];
    int lane = threadIdx.x & 31, wid = threadIdx.x >> 5;
    #pragma unroll
    for (int o = 16; o; o >>= 1) v += __shfl_down_sync(~0u, v, o);
    if (!lane) ws[wid] = v;
    __syncthreads();
    if (!wid) {
        int s = ws[lane];
        #pragma unroll
        for (int o = 16; o; o >>= 1) s += __shfl_down_sync(~0u, s, o);
        if (!lane) g_bsum[r * NB + blockIdx.x] = s;
    }
}

// ---------------- scan phase C: full exclusive scan + rs + cursor init ----------------
__global__ void k_scanC() {
    int r = blockIdx.y;
    int i = blockIdx.x * 1024 + threadIdx.x;
    int t = threadIdx.x;
    int lane = t & 31, wid = t >> 5;

    // prefix of block sums (each block computes its own; NB=98 values)
    __shared__ int wsum[4];
    __shared__ int s_pre;
    if (t < 128) {
        int pv = (t < blockIdx.x) ? g_bsum[r * NB + t] : 0;   // blockIdx.x <= 97 < 128
        #pragma unroll
        for (int o = 16; o; o >>= 1) pv += __shfl_down_sync(~0u, pv, o);
        if (!lane) wsum[wid] = pv;
    }
    __syncthreads();
    if (t == 0) s_pre = wsum[0] + wsum[1] + wsum[2] + wsum[3];

    int v = (i < NNODE) ? g_cnt_in[r * NNODE + i] : 0;
    int incl = v;
    #pragma unroll
    for (int o = 1; o < 32; o <<= 1) { int x = __shfl_up_sync(~0u, incl, o); if (lane >= o) incl += x; }
    __shared__ int ws[32];
    if (lane == 31) ws[wid] = incl;
    __syncthreads();
    if (wid == 0) {
        int s = ws[lane];
        #pragma unroll
        for (int o = 1; o < 32; o <<= 1) { int x = __shfl_up_sync(~0u, s, o); if (lane >= o) s += x; }
        ws[lane] = s;
    }
    __syncthreads();
    int base = s_pre + (wid ? ws[wid - 1] : 0);
    if (i < NNODE) {
        int excl = base + incl - v;
        g_rowstart[r * (NNODE + 1) + i] = excl;
        g_cursor [r * NNODE + i] = excl;                 // write position for CSR fill
        g_rs_in  [r * NNODE + i] = rsqrtf(fmaxf((float)v, 1.f));
        g_rs_out [r * NNODE + i] = rsqrtf(fmaxf((float)g_cnt_out[r * NNODE + i], 1.f));
        if (i == NNODE - 1) g_rowstart[r * (NNODE + 1) + NNODE] = base + incl;
    }
}

// ---------------- CSR fill (by destination), cursor holds absolute write pos ----------------
__global__ void k_csr(const int* __restrict__ edges) {
    int i = blockIdx.x * blockDim.x + threadIdx.x;
    if (i >= RNUM * NEDGE) return;
    int r = i / NEDGE, e = i % NEDGE;
    int src = edges[(size_t)r * 2 * NEDGE + e];
    int dst = edges[(size_t)r * 2 * NEDGE + NEDGE + e];
    int pos = atomicAdd(&g_cursor[r * NNODE + dst], 1);
    g_csr[r * NEDGE + pos] = src;
}

// ---------------- tf32 helpers ----------------
__device__ __forceinline__ unsigned f2tf(float x) {
    unsigned r;
    asm("cvt.rna.tf32.f32 %0, %1;" : "=r"(r) : "f"(x));
    return r;
}

__device__ __forceinline__ void mma_tf32(float c[4], unsigned a0, unsigned a1, unsigned a2,
                                         unsigned a3, unsigned b0, unsigned b1) {
    asm volatile("mma.sync.aligned.m16n8k8.row.col.f32.tf32.tf32.f32 "
                 "{%0,%1,%2,%3}, {%4,%5,%6,%7}, {%8,%9}, {%0,%1,%2,%3};"
                 : "+f"(c[0]), "+f"(c[1]), "+f"(c[2]), "+f"(c[3])
                 : "r"(a0), "r"(a1), "r"(a2), "r"(a3), "r"(b0), "r"(b1));
}

// ---------------- FUSED layer: aggregate per relation into smem A-tile (tf32),
// ---------------- MMA-accumulate across relations, bias+relu, store h ----------------
// block = 128 nodes, 512 threads (16 warps). dynamic smem: As[128][132] + Bs[128][132] (u32 tf32 bits)
__global__ __launch_bounds__(512) void k_layer(const float* __restrict__ ext, int use_ext,
                                               int inbuf, const float* __restrict__ W,
                                               const float* __restrict__ bias, int outbuf) {
    extern __shared__ unsigned smem[];
    unsigned* As = smem;                 // As[row*LPAD + k]
    unsigned* Bs = smem + 128 * LPAD;    // Bs[col*LPAD + k]
    const float* hin = use_ext ? ext : (g_h + (size_t)inbuf * NNODE * DH);
    float* C = g_h + (size_t)outbuf * NNODE * DH;

    int tid = threadIdx.x;
    int warp = tid >> 5, lane = tid & 31;
    int warpM = warp >> 2, warpN = warp & 3;   // 4 x 4 warp grid
    int qr = lane >> 2, qc = lane & 3;
    int row0 = blockIdx.x * 128;

    float c[2][4][4];
    #pragma unroll
    for (int m = 0; m < 2; m++)
        #pragma unroll
        for (int n = 0; n < 4; n++)
            #pragma unroll
            for (int k = 0; k < 4; k++) c[m][n][k] = 0.f;

    for (int r = 0; r < RNUM; r++) {
        __syncthreads();   // As/Bs free (prev relation MMA done)

        // --- load W_r[k][col] -> Bs[col][k] (tf32), conflict-free stores ---
        const float* Wr = W + (size_t)r * DH * DH;
        #pragma unroll
        for (int it = 0; it < 8; it++) {
            int linear = tid + it * 512;          // 0..4095 float4 units
            int k  = linear & 127;
            int c4 = (linear >> 7) << 2;          // 0,4,...,124
            float4 w = *(const float4*)(Wr + (size_t)k * DH + c4);
            Bs[(c4 + 0) * LPAD + k] = f2tf(w.x);
            Bs[(c4 + 1) * LPAD + k] = f2tf(w.y);
            Bs[(c4 + 2) * LPAD + k] = f2tf(w.z);
            Bs[(c4 + 3) * LPAD + k] = f2tf(w.w);
        }

        // --- aggregate relation r for 128 nodes: warp w handles rows w*8..w*8+7 ---
        for (int nn = 0; nn < 8; nn++) {
            int rowLocal = warp * 8 + nn;
            int n = row0 + rowLocal;
            float4 acc = make_float4(0.f, 0.f, 0.f, 0.f);
            if (n < NNODE) {
                int beg = __ldg(&g_rowstart[r * (NNODE + 1) + n]);
                int end = __ldg(&g_rowstart[r * (NNODE + 1) + n + 1]);
                int e = beg;
                int src_n = 0; float sc_n = 0.f;
                if (e < end) {
                    src_n = __ldg(&g_csr[r * NEDGE + e]);
                    sc_n  = __ldg(&g_rs_out[r * NNODE + src_n]);
                }
                while (e < end) {
                    int src = src_n; float sc = sc_n;
                    int e1 = e + 1;
                    if (e1 < end) {
                        src_n = __ldg(&g_csr[r * NEDGE + e1]);
                        sc_n  = __ldg(&g_rs_out[r * NNODE + src_n]);
                    }
                    float4 hv = __ldg((const float4*)(hin + (size_t)src * DH) + lane);
                    acc.x += sc * hv.x; acc.y += sc * hv.y;
                    acc.z += sc * hv.z; acc.w += sc * hv.w;
                    e = e1;
                }
                float si = __ldg(&g_rs_in[r * NNODE + n]);
                acc.x *= si; acc.y *= si; acc.z *= si; acc.w *= si;
            }
            uint4 u;
            u.x = f2tf(acc.x); u.y = f2tf(acc.y); u.z = f2tf(acc.z); u.w = f2tf(acc.w);
            *(uint4*)&As[rowLocal * LPAD + lane * 4] = u;
        }
        __syncthreads();

        // --- MMA over this relation's K=128 ---
        #pragma unroll
        for (int kk = 0; kk < 128; kk += 8) {
            unsigned bfr[4][2];
            #pragma unroll
            for (int n = 0; n < 4; n++) {
                int col = warpN * 32 + n * 8 + qr;
                bfr[n][0] = Bs[col * LPAD + kk + qc];
                bfr[n][1] = Bs[col * LPAD + kk + qc + 4];
            }
            #pragma unroll
            for (int m = 0; m < 2; m++) {
                int row = warpM * 32 + m * 16;
                unsigned a0 = As[(row + qr)     * LPAD + kk + qc];
                unsigned a1 = As[(row + qr + 8) * LPAD + kk + qc];
                unsigned a2 = As[(row + qr)     * LPAD + kk + qc + 4];
                unsigned a3 = As[(row + qr + 8) * LPAD + kk + qc + 4];
                #pragma unroll
                for (int n = 0; n < 4; n++)
                    mma_tf32(c[m][n], a0, a1, a2, a3, bfr[n][0], bfr[n][1]);
            }
        }
    }

    // --- epilogue: bias sum over relations + relu, float2 stores ---
    #pragma unroll
    for (int n = 0; n < 4; n++) {
        int gc = warpN * 32 + n * 8 + 2 * qc;
        float b0v = bias[gc]     + bias[DH + gc]     + bias[2 * DH + gc]     + bias[3 * DH + gc];
        float b1v = bias[gc + 1] + bias[DH + gc + 1] + bias[2 * DH + gc + 1] + bias[3 * DH + gc + 1];
        #pragma unroll
        for (int m = 0; m < 2; m++) {
            int gr0 = row0 + warpM * 32 + m * 16 + qr;
            if (gr0 < NNODE) {
                float2 v; v.x = fmaxf(c[m][n][0] + b0v, 0.f); v.y = fmaxf(c[m][n][1] + b1v, 0.f);
                *(float2*)(C + (size_t)gr0 * DH + gc) = v;
            }
            int gr1 = gr0 + 8;
            if (gr1 < NNODE) {
                float2 v; v.x = fmaxf(c[m][n][2] + b0v, 0.f); v.y = fmaxf(c[m][n][3] + b1v, 0.f);
                *(float2*)(C + (size_t)gr1 * DH + gc) = v;
            }
        }
    }
}

// ---------------- avg pooling over sorted graph_ids ----------------
__global__ void k_pool(const int* __restrict__ gid, int buf) {
    const float* h = g_h + (size_t)buf * NNODE * DH;
    int nb = gridDim.x;
    int chunk = (NNODE + nb - 1) / nb;
    int beg = blockIdx.x * chunk;
    int end = min(beg + chunk, NNODE);
    if (beg >= end) return;
    int f = threadIdx.x;
    int cur = gid[beg];
    float acc = 0.f; int cnt = 0;
    for (int i = beg; i < end; i++) {
        int g = gid[i];
        if (g != cur) {
            atomicAdd(&g_hg[cur * DH + f], acc);
            if (f == 0) atomicAdd(&g_gcnt[cur], cnt);
            acc = 0.f; cnt = 0; cur = g;
        }
        acc += h[(size_t)i * DH + f];
        cnt++;
    }
    atomicAdd(&g_hg[cur * DH + f], acc);
    if (f == 0) atomicAdd(&g_gcnt[cur], cnt);
}

// ---------------- classifier ----------------
__global__ void k_cls(const float* __restrict__ Wc, const float* __restrict__ bc,
                      float* __restrict__ out) {
    int g = blockIdx.x;
    __shared__ float row[DH];
    int t = threadIdx.x;
    float inv = 1.f / fmaxf((float)g_gcnt[g], 1.f);
    row[t] = g_hg[g * DH + t] * inv;
    __syncthreads();
    if (t < NC) {
        float s = bc[t];
        #pragma unroll 16
        for (int k = 0; k < DH; k++) s += row[k] * Wc[k * NC + t];
        out[g * NC + t] = s;
    }
}

// ---------------- launch ----------------
extern "C" void kernel_launch(void* const* d_in, const int* in_sizes, int n_in,
                              void* d_out, int out_size) {
    const float* features = (const float*)d_in[0];
    const int*   edges    = (const int*)d_in[1];
    const int*   gid      = (const int*)d_in[2];
    const float* W0       = (const float*)d_in[3];
    const float* b0       = (const float*)d_in[4];
    const float* Wl       = (const float*)d_in[5];
    const float* bl       = (const float*)d_in[6];
    const float* Wc       = (const float*)d_in[7];
    const float* bc       = (const float*)d_in[8];
    float* out = (float*)d_out;

    cudaFuncSetAttribute(k_layer, cudaFuncAttributeMaxDynamicSharedMemorySize, SMEM_BYTES);

    // graph structure (recomputed each launch — no caching allowed)
    k_zero <<<(RNUM * NNODE + 255) / 256, 256>>>();
    k_count<<<(RNUM * NEDGE + 255) / 256, 256>>>(edges);
    k_scanA<<<dim3(NB, RNUM), 1024>>>();
    k_scanC<<<dim3(NB, RNUM), 1024>>>();
    k_csr  <<<(RNUM * NEDGE + 255) / 256, 256>>>(edges);

    const int layerBlocks = (NNODE + 127) / 128;

    // fused layers (launch index 5 = first k_layer, so ncu -s 5 profiles it)
    k_layer<<<layerBlocks, 512, SMEM_BYTES>>>(features, 1, 0, W0, b0, 0);
    k_layer<<<layerBlocks, 512, SMEM_BYTES>>>(nullptr, 0, 0, Wl, bl, 1);
    k_layer<<<layerBlocks, 512, SMEM_BYTES>>>(nullptr, 0, 1, Wl + 4 * DH * DH, bl + 4 * DH, 0);

    // pooling + classifier
    k_pool<<<784, DH>>>(gid, 0);
    k_cls <<<GNUM, DH>>>(Wc, bc, out);
}